// round 3
// baseline (speedup 1.0000x reference)
#include <cuda_runtime.h>
#include <cuda_bf16.h>

// BatchRNNCustom: pack padded (B,S,D) sequences by descending length.
//   sorted_indices   = stable argsort(-lengths)
//   unsorted_indices = inverse permutation
//   batch_sizes[t]   = #{b : len_b > t}
//   packed[offsets[t] + b_sorted] = inputs[sorted_indices[b_sorted], t]
// Rows >= sum(lengths) are zero.
//
// Output layout (fp32, concatenated in reference return order):
//   [0, B*S*D)                 packed_data
//   [B*S*D, B*S*D+S)           batch_sizes
//   [.. +B)                    sorted_indices
//   [.. +B)                    unsorted_indices
// Tail writes are guarded by out_size.
//
// NOTE: lengths dtype is detected at runtime. JAX with x64 disabled turns
// jnp.int64 into int32 silently; we must handle both. Lengths are >= 1, so
// if the int32 view has all odd-indexed words == 0, the buffer is int64.

#define BB 64
#define SS 2048
#define DD 512

__device__ int g_sortidx[BB];     // g_sortidx[rank] = original batch index
__device__ int g_sortlen[BB];     // lengths sorted descending
__device__ int g_offsets[SS + 1]; // offsets[t] = sum_b min(len_b, t)

// ---------------------------------------------------------------------------
// Kernel 1: stable descending rank sort of 64 lengths (O(B^2), one block).
// rank[i] = #{j : len_j > len_i  or (len_j == len_i and j < i)}  -> stable.
// Also emits sorted_indices / unsorted_indices into the output tail.
// ---------------------------------------------------------------------------
__global__ void sort_kernel(const int* __restrict__ lengths_raw,
                            float* __restrict__ out, long long out_size) {
    __shared__ int slen[BB];
    __shared__ int s_is64;
    int i = threadIdx.x;            // 64 threads

    // --- dtype detection: int32 vs int64 (little-endian) ---
    if (i == 0) s_is64 = 1;
    __syncthreads();
    // words 0..63 cover all 64 int32 lengths, or the first 32 int64 lengths.
    int w = lengths_raw[i];
    if ((i & 1) && w != 0) atomicAnd(&s_is64, 0);  // odd word nonzero -> int32
    __syncthreads();

    if (s_is64) {
        const long long* l64 = (const long long*)lengths_raw;
        slen[i] = (int)l64[i];
    } else {
        slen[i] = lengths_raw[i];
    }
    __syncthreads();

    int li = slen[i];
    int r = 0;
#pragma unroll 8
    for (int j = 0; j < BB; j++) {
        int lj = slen[j];
        if (lj > li || (lj == li && j < i)) r++;
    }
    g_sortidx[r] = i;
    g_sortlen[r] = li;

    long long tail = (long long)BB * SS * DD + SS;
    if (out_size >= tail + 2 * BB) {
        out[tail + r] = (float)i;        // sorted_indices[r]   = i
        out[tail + BB + i] = (float)r;   // unsorted_indices[i] = r
    }
}

// ---------------------------------------------------------------------------
// Kernel 2: per-t offsets and batch sizes, no scan dependency:
//   offsets[t] = sum_b min(len_b, t);  batch_sizes[t] = #{len_b > t}
// ---------------------------------------------------------------------------
__global__ void offsets_kernel(float* __restrict__ out, long long out_size) {
    __shared__ int slen[BB];
    if (threadIdx.x < BB) slen[threadIdx.x] = g_sortlen[threadIdx.x];
    __syncthreads();

    int t = blockIdx.x * blockDim.x + threadIdx.x;
    if (t > SS) return;

    int off = 0, cnt = 0;
#pragma unroll 8
    for (int j = 0; j < BB; j++) {
        int l = slen[j];
        off += (l < t) ? l : t;
        cnt += (l > t) ? 1 : 0;
    }
    g_offsets[t] = off;

    if (t < SS) {
        long long base = (long long)BB * SS * DD;
        if (out_size >= base + SS) out[base + t] = (float)cnt;
    }
}

// ---------------------------------------------------------------------------
// Kernel 3: destination-domain pack. One 128-thread block per output row
// (2 KB, 128 x float4). Rows >= total are zeroed; valid rows binary-search
// offsets (uniform-address loads, warp-broadcast, L1-resident) to recover
// (t, b_sorted), then stream-copy the source row.
// ---------------------------------------------------------------------------
__global__ void __launch_bounds__(128) pack_kernel(const float* __restrict__ in,
                                                   float* __restrict__ out) {
    const int r = blockIdx.x;                 // destination row, 0 .. B*S-1
    const int tid = threadIdx.x;              // 0 .. 127
    float4* dst = reinterpret_cast<float4*>(out) + (long long)r * (DD / 4) + tid;

    const int total = g_offsets[SS];
    if (r >= total) {
        *dst = make_float4(0.f, 0.f, 0.f, 0.f);
        return;
    }

    // last t with offsets[t] <= r  (invariant: offsets[lo] <= r < offsets[hi])
    int lo = 0, hi = SS;
    while (hi - lo > 1) {
        int mid = (lo + hi) >> 1;
        if (g_offsets[mid] <= r) lo = mid; else hi = mid;
    }
    const int t = lo;
    const int b = r - g_offsets[t];           // sorted batch position
    const int src = g_sortidx[b];             // original batch index

    const float4* srcp = reinterpret_cast<const float4*>(in)
                       + ((long long)src * SS + t) * (DD / 4) + tid;
    *dst = *srcp;
}

extern "C" void kernel_launch(void* const* d_in, const int* in_sizes, int n_in,
                              void* d_out, int out_size) {
    const float* inputs = (const float*)d_in[0];       // (B, S, D) fp32
    // d_in[1]: input_paddings (unused — all zeros, lengths carry the info)
    const int* lengths_raw = (const int*)d_in[2];      // (B,) int32 OR int64
    float* out = (float*)d_out;
    long long osz = (long long)out_size;

    sort_kernel<<<1, BB>>>(lengths_raw, out, osz);
    offsets_kernel<<<(SS + 1 + 255) / 256, 256>>>(out, osz);
    pack_kernel<<<BB * SS, 128>>>(inputs, out);
}

// round 4
// speedup vs baseline: 1.5584x; 1.5584x over previous
#include <cuda_runtime.h>
#include <cuda_bf16.h>

// BatchRNNCustom: pack padded (B,S,D) sequences by descending length.
// Output layout (fp32, concatenated in reference return order):
//   [0, B*S*D)            packed_data
//   [B*S*D, +S)           batch_sizes
//   [.. +B)               sorted_indices
//   [.. +B)               unsorted_indices
//
// Pipeline:
//   1) meta_kernel : dtype-detect lengths, stable descending rank-sort (B=64),
//                    offsets[t] = sum_b min(len_b,t), aux outputs. 1 block.
//   2) map_kernel  : row r in [0,total) -> (t, original batch) LUT (1 MB).
//   3) pack_kernel : 4 rows per 128-thread block, MLP=4 float4 streaming
//                    gather/scatter with .cs hints. Rows >= total are zeroed.

#define BB 64
#define SS 2048
#define DD 512

__device__ int  g_sortidx[BB];      // rank -> original batch index
__device__ int  g_offsets[SS + 1];  // offsets[t] = sum_b min(len_b, t)
__device__ int2 g_map[BB * SS];     // valid row r -> {t, src_batch}

// ---------------------------------------------------------------------------
// Kernel 1: metadata. Single block, 1024 threads.
// ---------------------------------------------------------------------------
__global__ void meta_kernel(const int* __restrict__ lengths_raw,
                            float* __restrict__ out, long long out_size) {
    __shared__ int sraw[BB];    // lengths by original index
    __shared__ int slen[BB];    // lengths sorted descending
    __shared__ int s_is64;
    const int tid = threadIdx.x;

    // dtype detection: lengths >= 1, so int64 (LE) has all odd words == 0.
    if (tid == 0) s_is64 = 1;
    __syncthreads();
    if (tid < BB) {
        int w = lengths_raw[tid];
        if ((tid & 1) && w != 0) atomicAnd(&s_is64, 0);
    }
    __syncthreads();
    if (tid < BB) {
        sraw[tid] = s_is64 ? (int)((const long long*)lengths_raw)[tid]
                           : lengths_raw[tid];
    }
    __syncthreads();

    // stable descending rank sort (O(B^2))
    if (tid < BB) {
        int li = sraw[tid];
        int r = 0;
#pragma unroll 8
        for (int j = 0; j < BB; j++) {
            int lj = sraw[j];
            if (lj > li || (lj == li && j < tid)) r++;
        }
        slen[r] = li;
        g_sortidx[r] = tid;

        long long tail = (long long)BB * SS * DD + SS;
        if (out_size >= tail + 2 * BB) {
            out[tail + r] = (float)tid;       // sorted_indices[r]   = tid
            out[tail + BB + tid] = (float)r;  // unsorted_indices[tid] = r
        }
    }
    __syncthreads();

    // offsets[t] and batch_sizes[t], no scan dependency
    const long long base = (long long)BB * SS * DD;
    for (int t = tid; t <= SS; t += blockDim.x) {
        int off = 0, cnt = 0;
#pragma unroll 8
        for (int j = 0; j < BB; j++) {
            int l = slen[j];
            off += (l < t) ? l : t;
            cnt += (l > t) ? 1 : 0;
        }
        g_offsets[t] = off;
        if (t < SS && out_size >= base + SS) out[base + t] = (float)cnt;
    }
}

// ---------------------------------------------------------------------------
// Kernel 2: fill row -> (t, src_batch) LUT. One thread per (t, b) pair.
// ---------------------------------------------------------------------------
__global__ void map_kernel() {
    int idx = blockIdx.x * blockDim.x + threadIdx.x;   // 0 .. B*S-1
    int t = idx >> 6;          // / BB
    int b = idx & (BB - 1);    // % BB
    int off = g_offsets[t];
    int cnt = g_offsets[t + 1] - off;
    if (b < cnt) g_map[off + b] = make_int2(t, g_sortidx[b]);
}

// ---------------------------------------------------------------------------
// Kernel 3: pack. 128-thread block handles 4 consecutive output rows
// (4 x 2 KB). MLP=4 independent float4 streaming loads, then 4 streaming
// stores into an 8 KB contiguous destination region.
// ---------------------------------------------------------------------------
__global__ void __launch_bounds__(128) pack_kernel(const float* __restrict__ in,
                                                   float* __restrict__ out) {
    const int tid = threadIdx.x;
    const int r0 = blockIdx.x * 4;
    const int total = g_offsets[SS];
    const float4* inp = reinterpret_cast<const float4*>(in);

    float4 v[4];
#pragma unroll
    for (int i = 0; i < 4; i++) {
        const int r = r0 + i;
        if (r < total) {
            int2 m = g_map[r];   // uniform per block-slot: {t, src_batch}
            long long srow = (long long)m.y * SS + m.x;
            v[i] = __ldcs(inp + srow * (DD / 4) + tid);
        } else {
            v[i] = make_float4(0.f, 0.f, 0.f, 0.f);
        }
    }

    float4* op = reinterpret_cast<float4*>(out) + (long long)r0 * (DD / 4) + tid;
#pragma unroll
    for (int i = 0; i < 4; i++) __stcs(op + i * (DD / 4), v[i]);
}

extern "C" void kernel_launch(void* const* d_in, const int* in_sizes, int n_in,
                              void* d_out, int out_size) {
    const float* inputs = (const float*)d_in[0];    // (B, S, D) fp32
    // d_in[1]: input_paddings (unused — all zeros)
    const int* lengths_raw = (const int*)d_in[2];   // (B,) int32 or int64
    float* out = (float*)d_out;
    long long osz = (long long)out_size;

    meta_kernel<<<1, 1024>>>(lengths_raw, out, osz);
    map_kernel<<<(BB * SS) / 256, 256>>>();
    pack_kernel<<<(BB * SS) / 4, 128>>>(inputs, out);
}